// round 2
// baseline (speedup 1.0000x reference)
#include <cuda_runtime.h>

// ---------------- problem constants ----------------
#define TWO_PI_D 6.283185307179586
#define C_M  ((float)(1.0/(TWO_PI_D*128.0)))   // 1/(2pi*s1), s1=128 ; also c_g
#define C_H  ((float)(1.0/(TWO_PI_D*96.0)))    // 1/(2pi*s2), s2=96
#define C_V  ((float)((1.0/(TWO_PI_D*96.0))*(1.0/(TWO_PI_D*128.0))))
#define C_M2 ((float)((1.0/(TWO_PI_D*128.0))*(1.0/(TWO_PI_D*128.0))))

#define NB 8      // batch
#define NP 512    // points per image
#define KK 64     // grid per axis
#define GG 4096   // KK*KK
#define MMM 100   // M

// ---------------- scratch (__device__ globals; no allocs allowed) ----------------
__device__ float  g_vraw[NB*GG];
__device__ int    g_minds[NB*MMM];
__device__ float  g_vM[NB*MMM];
__device__ float4 g_xf[NB][NP][MMM];   // (xf, yf, P=xf^2+yf^2, mm=tmpm2)

// =====================================================================
// Kernel 1: v[b][g] via separable "GEMM" reductions over n.
//   Sv2[iy][ix]  = sum_n exp(-dy^2/192)*exp(-dx^2/192)
//   Sm2[iy][ix]  = sum_n exp(-dy^2/128)*exp(-dx^2/128)   (= (Ey1*Ex1)^2 sums)
//   v = C_V*Sv2 - C_M2*Sm2 ; raw v -> scratch, clamped v -> out.
// =====================================================================
__global__ void k_mv(const float* __restrict__ pts, float* __restrict__ out_v)
{
    int b = blockIdx.x, tid = threadIdx.x;
    __shared__ float sEx2[32][68], sEy2[32][68], sEx1q[32][68], sEy1q[32][68];
    int ox = (tid & 15) << 2, oy = (tid >> 4) << 2;
    float accv[16], accm[16];
#pragma unroll
    for (int q = 0; q < 16; q++) { accv[q] = 0.f; accm[q] = 0.f; }

    for (int c = 0; c < 16; c++) {
        __syncthreads();
        for (int idx = tid; idx < 2048; idx += 256) {
            int nl = idx >> 6, j = idx & 63;
            int n = (c << 5) + nl;
            float x = pts[(((b << 9) + n) << 1) + 0];
            float y = pts[(((b << 9) + n) << 1) + 1];
            float cd = 8.0f * (float)j + 4.0f;
            float dx = x - cd, dy = y - cd;
            float d2x = dx * dx, d2y = dy * dy;
            float e1x = expf(-d2x * (1.0f/256.0f));
            float e1y = expf(-d2y * (1.0f/256.0f));
            sEx1q[nl][j] = e1x * e1x;
            sEy1q[nl][j] = e1y * e1y;
            sEx2[nl][j]  = expf(-d2x * (1.0f/192.0f));
            sEy2[nl][j]  = expf(-d2y * (1.0f/192.0f));
        }
        __syncthreads();
#pragma unroll 4
        for (int nl = 0; nl < 32; nl++) {
            float4 ex2 = *(const float4*)&sEx2[nl][ox];
            float4 ey2 = *(const float4*)&sEy2[nl][oy];
            float4 ex1 = *(const float4*)&sEx1q[nl][ox];
            float4 ey1 = *(const float4*)&sEy1q[nl][oy];
            float ex2a[4] = {ex2.x, ex2.y, ex2.z, ex2.w};
            float ey2a[4] = {ey2.x, ey2.y, ey2.z, ey2.w};
            float ex1a[4] = {ex1.x, ex1.y, ex1.z, ex1.w};
            float ey1a[4] = {ey1.x, ey1.y, ey1.z, ey1.w};
#pragma unroll
            for (int a = 0; a < 4; a++)
#pragma unroll
                for (int bb = 0; bb < 4; bb++) {
                    accv[a*4+bb] += ey2a[a] * ex2a[bb];
                    accm[a*4+bb] += ey1a[a] * ex1a[bb];
                }
        }
    }
#pragma unroll
    for (int a = 0; a < 4; a++)
#pragma unroll
        for (int bb = 0; bb < 4; bb++) {
            int g = (oy + a) * 64 + ox + bb;
            float v = C_V * accv[a*4+bb] - C_M2 * accm[a*4+bb];
            g_vraw[b*GG + g] = v;
            out_v[b*GG + g]  = fmaxf(v, 1e-6f);
        }
}

// =====================================================================
// Kernel 2: m[b][n][g] = C_M * Ey1[n][iy] * Ex1[n][ix].  Pure HBM write.
// =====================================================================
__global__ void k_m(const float* __restrict__ pts, float* __restrict__ out_m)
{
    int bn = blockIdx.x, tid = threadIdx.x;
    __shared__ float ex[64], ey[64];
    float x = pts[2*bn], y = pts[2*bn + 1];
    if (tid < 64) {
        float cd = 8.0f * (float)tid + 4.0f;
        float dx = x - cd;
        ex[tid] = expf(-dx*dx * (1.0f/256.0f));
    } else if (tid < 128) {
        int j = tid - 64;
        float cd = 8.0f * (float)j + 4.0f;
        float dy = y - cd;
        ey[j] = expf(-dy*dy * (1.0f/256.0f));
    }
    __syncthreads();
    float4* mrow = (float4*)(out_m + (size_t)bn * GG);
    for (int i = tid; i < 1024; i += 128) {
        int g0 = i << 2;
        int iy = g0 >> 6, ix = g0 & 63;
        float e = C_M * ey[iy];
        mrow[i] = make_float4(e*ex[ix], e*ex[ix+1], e*ex[ix+2], e*ex[ix+3]);
    }
}

// =====================================================================
// Kernel 3: top-100 selection. Bitonic sort of (value desc, idx asc) keys
// == stable argsort(-v); then ascending sort of the 100 indices.
// =====================================================================
__device__ __forceinline__ unsigned int fordu(float f)
{
    unsigned int u = __float_as_uint(f);
    return (u & 0x80000000u) ? ~u : (u | 0x80000000u);
}

__global__ void k_sort(float* __restrict__ out_minds)
{
    int b = blockIdx.x, tid = threadIdx.x;
    __shared__ unsigned long long keys[4096];
    __shared__ unsigned int top[128];
    for (int i = tid; i < 4096; i += 512) {
        float v = g_vraw[b*GG + i];
        keys[i] = ((unsigned long long)(~fordu(v)) << 32) | (unsigned int)i;
    }
    for (int k = 2; k <= 4096; k <<= 1)
        for (int j = k >> 1; j > 0; j >>= 1) {
            __syncthreads();
            for (int i = tid; i < 4096; i += 512) {
                int ixj = i ^ j;
                if (ixj > i) {
                    unsigned long long a = keys[i], c = keys[ixj];
                    bool up = ((i & k) == 0);
                    if ((a > c) == up) { keys[i] = c; keys[ixj] = a; }
                }
            }
        }
    __syncthreads();
    if (tid < 128)
        top[tid] = (tid < 100) ? (unsigned int)(keys[tid] & 0xFFFFFFFFu) : 0xFFFFFFFFu;
    for (int k = 2; k <= 128; k <<= 1)
        for (int j = k >> 1; j > 0; j >>= 1) {
            __syncthreads();
            if (tid < 128) {
                int i = tid, ixj = i ^ j;
                if (ixj > i) {
                    unsigned int a = top[i], c = top[ixj];
                    bool up = ((i & k) == 0);
                    if ((a > c) == up) { top[i] = c; top[ixj] = a; }
                }
            }
        }
    __syncthreads();
    if (tid < 100) {
        int mind = (int)top[tid];
        g_minds[b*MMM + tid] = mind;
        out_minds[b*MMM + tid] = (float)mind;
        float vr = g_vraw[b*GG + mind];
        g_vM[b*MMM + tid] = fmaxf(vr, 1e-6f) + 1e-10f;
    }
}

// =====================================================================
// Kernel 4: gather per (b,n,a): xf, yf, P = disM, mm = tmpm2.
// =====================================================================
__global__ void k_gather(const float* __restrict__ pts)
{
    int b = blockIdx.y, c = blockIdx.x, tid = threadIdx.x;
    __shared__ int sm[100];
    if (tid < 100) sm[tid] = g_minds[b*MMM + tid];
    __syncthreads();
    for (int idx = tid; idx < 64*100; idx += 256) {
        int a = idx % 100, nl = idx / 100;
        int n = (c << 6) + nl;
        int mind = sm[a];
        int iy = mind >> 6, ix = mind & 63;
        float x = pts[(((b << 9) + n) << 1) + 0];
        float y = pts[(((b << 9) + n) << 1) + 1];
        float xf = x - (8.0f*(float)ix + 4.0f);
        float yf = y - (8.0f*(float)iy + 4.0f);
        float P = xf*xf + yf*yf;
        float mm = C_M * expf(-P * (1.0f/256.0f));
        g_xf[b][n][a] = make_float4(xf, yf, P, mm);
    }
}

// =====================================================================
// Kernel 5: A matrix. For i<j: reduce over n using
//   arg1  = (2Q - S)/256,  arg12 = (Q - S)/192,  Smm += mm_i*mm_j
//   A[i][j] = C_M*(C_H*S12 + S1) - Smm ; diag = 1e-10.
// =====================================================================
__global__ void k_pairs(float* __restrict__ out_A)
{
    int b = blockIdx.y, tid = threadIdx.x;
    int p = blockIdx.x * 256 + tid;
    bool active = (p < 4950);
    int i = 0, j = 0;
    if (active) {
        float pf = (float)p;
        i = (int)floorf((199.0f - sqrtf(39601.0f - 8.0f*pf)) * 0.5f);
        if (i < 0) i = 0;
        if (i > 98) i = 98;
        while (i < 98 && (i+1)*(199-(i+1))/2 <= p) i++;
        while (i > 0 && i*(199-i)/2 > p) i--;
        j = i + 1 + (p - i*(199-i)/2);
    }
    __shared__ float4 sx[16][100];
    float a1 = 0.f, a12 = 0.f, amm = 0.f;
    for (int c = 0; c < 32; c++) {
        __syncthreads();
        for (int idx = tid; idx < 1600; idx += 256)
            sx[idx/100][idx%100] = g_xf[b][(c << 4) + idx/100][idx%100];
        __syncthreads();
        if (active) {
#pragma unroll
            for (int nl = 0; nl < 16; nl++) {
                float4 di = sx[nl][i];
                float4 dj = sx[nl][j];
                float Q = di.x*dj.x + di.y*dj.y;
                float S = di.z + dj.z;
                a1  += __expf((2.0f*Q - S) * (1.0f/256.0f));
                a12 += __expf((Q - S) * (1.0f/192.0f));
                amm += di.w * dj.w;
            }
        }
    }
    if (active) {
        float Aij = C_M * (C_H * a12 + a1) - amm;
        out_A[b*10000 + i*100 + j] = Aij;
        out_A[b*10000 + j*100 + i] = Aij;
    }
    if (blockIdx.x == 0 && tid < 100)
        out_A[b*10000 + tid*101] = 1e-10f;
}

// =====================================================================
// Kernel 6: per batch, fp64 in-smem Gauss-Jordan (partial pivoting):
//   invA = inv(A); tmpA = vM_i*invA*vM_j + diag(vM); Bm = inv(tmpA).
// =====================================================================
__global__ void k_inv(const float* __restrict__ out_A, float* __restrict__ out_Bm)
{
    extern __shared__ double dsm[];
    double (*sA)[101] = (double(*)[101])dsm;
    double* rowk = dsm + 100*101;
    double* colk = rowk + 100;
    double* svm  = colk + 100;
    __shared__ int piv[100];
    __shared__ double redv[8];
    __shared__ int redi[8];
    __shared__ int s_pr;
    __shared__ double s_pinv;

    int b = blockIdx.x, tid = threadIdx.x;
    for (int idx = tid; idx < 10000; idx += 256)
        sA[idx/100][idx%100] = (double)out_A[b*10000 + idx];
    if (tid < 100) svm[tid] = (double)g_vM[b*MMM + tid];
    __syncthreads();

    for (int pass = 0; pass < 2; pass++) {
        for (int k = 0; k < 100; k++) {
            // --- partial pivot search on column k, rows [k,100) ---
            double bv = -1.0; int br = k + tid;
            if (tid < 100 - k) bv = fabs(sA[k + tid][k]);
#pragma unroll
            for (int off = 16; off; off >>= 1) {
                double ov = __shfl_down_sync(0xFFFFFFFFu, bv, off);
                int    oi = __shfl_down_sync(0xFFFFFFFFu, br, off);
                if (ov > bv || (ov == bv && oi < br)) { bv = ov; br = oi; }
            }
            if ((tid & 31) == 0) { redv[tid >> 5] = bv; redi[tid >> 5] = br; }
            __syncthreads();
            if (tid == 0) {
                double b2 = redv[0]; int r2 = redi[0];
                for (int q = 1; q < 8; q++)
                    if (redv[q] > b2 || (redv[q] == b2 && redi[q] < r2)) { b2 = redv[q]; r2 = redi[q]; }
                s_pr = r2; piv[k] = r2;
                s_pinv = 1.0 / sA[r2][k];
            }
            __syncthreads();
            int pr = s_pr;
            double pinv = s_pinv;
            if (pr != k) {
                for (int jj = tid; jj < 100; jj += 256) {
                    double t = sA[k][jj]; sA[k][jj] = sA[pr][jj]; sA[pr][jj] = t;
                }
            }
            __syncthreads();
            // scale pivot row (a[k][k] <- pinv), snapshot row/col, zero column k
            for (int jj = tid; jj < 100; jj += 256) {
                double val = (jj == k) ? pinv : sA[k][jj] * pinv;
                sA[k][jj] = val; rowk[jj] = val;
            }
            for (int rr = tid; rr < 100; rr += 256) {
                if (rr != k) { colk[rr] = sA[rr][k]; sA[rr][k] = 0.0; }
            }
            __syncthreads();
            // eliminate: a[r][j] -= colk[r]*rowk[j]  (j==k yields -f*pinv, correct)
            for (int idx = tid; idx < 10000; idx += 256) {
                int rr = idx / 100, jj = idx - rr*100;
                if (rr != k) sA[rr][jj] -= colk[rr] * rowk[jj];
            }
            __syncthreads();
        }
        // undo row swaps as column swaps, reverse order
        for (int k = 99; k >= 0; k--) {
            int pp = piv[k];
            if (pp != k) {
                for (int rr = tid; rr < 100; rr += 256) {
                    double t = sA[rr][k]; sA[rr][k] = sA[rr][pp]; sA[rr][pp] = t;
                }
            }
            __syncthreads();
        }
        if (pass == 0) {
            // tmpA = vM_i * invA * vM_j + diag(vM)
            for (int idx = tid; idx < 10000; idx += 256) {
                int ii = idx / 100, jj = idx - ii*100;
                double val = svm[ii] * sA[ii][jj] * svm[jj];
                if (ii == jj) val += svm[ii];
                sA[ii][jj] = val;
            }
            __syncthreads();
        }
    }
    for (int idx = tid; idx < 10000; idx += 256)
        out_Bm[b*10000 + idx] = (float)sA[idx/100][idx%100];
}

// =====================================================================
// launch
// =====================================================================
extern "C" void kernel_launch(void* const* d_in, const int* in_sizes, int n_in,
                              void* d_out, int out_size)
{
    const float* pts = (const float*)d_in[0];
    float* out       = (float*)d_out;
    float* out_m     = out;                                   // 8*512*4096
    float* out_v     = out_m + (size_t)NB*NP*GG;              // 8*4096
    float* out_A     = out_v + (size_t)NB*GG;                 // 8*100*100
    float* out_Bm    = out_A + (size_t)NB*MMM*MMM;            // 8*100*100
    float* out_minds = out_Bm + (size_t)NB*MMM*MMM;           // 8*100

    k_mv<<<NB, 256>>>(pts, out_v);
    k_m<<<NB*NP, 128>>>(pts, out_m);
    k_sort<<<NB, 512>>>(out_minds);
    k_gather<<<dim3(8, NB), 256>>>(pts);
    k_pairs<<<dim3(20, NB), 256>>>(out_A);

    const int inv_smem = (100*101 + 300) * (int)sizeof(double);  // 83200 B
    cudaFuncSetAttribute(k_inv, cudaFuncAttributeMaxDynamicSharedMemorySize, inv_smem);
    k_inv<<<NB, 256, inv_smem>>>(out_A, out_Bm);
}

// round 5
// speedup vs baseline: 2.0980x; 2.0980x over previous
#include <cuda_runtime.h>

// ---------------- problem constants ----------------
#define TWO_PI_D 6.283185307179586
#define C_M  ((float)(1.0/(TWO_PI_D*128.0)))   // 1/(2pi*s1), s1=128 ; also c_g
#define C_H  ((float)(1.0/(TWO_PI_D*96.0)))    // 1/(2pi*s2), s2=96
#define C_V  ((float)((1.0/(TWO_PI_D*96.0))*(1.0/(TWO_PI_D*128.0))))
#define C_M2 ((float)((1.0/(TWO_PI_D*128.0))*(1.0/(TWO_PI_D*128.0))))

#define NB 8      // batch
#define NP 512    // points per image
#define KK 64     // grid per axis
#define GG 4096   // KK*KK
#define MMM 100   // M

// ---------------- scratch (__device__ globals; no allocs allowed) ----------------
__device__ float  g_vraw[NB*GG];
__device__ int    g_minds[NB*MMM];
__device__ float  g_vM[NB*MMM];
__device__ float4 g_xf[NB][NP][MMM];   // (xf, yf, P=xf^2+yf^2, mm=tmpm2)

// =====================================================================
// Kernel 1: v[b][g] via separable reductions over n, tiled 16 iy-rows
// per block (32 blocks). Accumulation order per cell is bitwise
// identical to the monolithic version: serial chain over n = 0..511.
// =====================================================================
__global__ void k_mv(const float* __restrict__ pts, float* __restrict__ out_v)
{
    int b = blockIdx.y, tid = threadIdx.x;
    int iy0 = blockIdx.x << 4;           // 16 rows per block
    __shared__ float sEx2[32][64], sEx1q[32][64];
    __shared__ float sEy2[32][16], sEy1q[32][16];
    int ix4 = (tid & 15) << 2;           // 4 consecutive ix per thread
    int iyl = tid >> 4;                  // 1 iy per thread (0..15)
    float accv[4], accm[4];
#pragma unroll
    for (int q = 0; q < 4; q++) { accv[q] = 0.f; accm[q] = 0.f; }

    for (int c = 0; c < 16; c++) {
        __syncthreads();
        // Ex for all 64 columns, 32 points
        for (int idx = tid; idx < 2048; idx += 256) {
            int nl = idx >> 6, j = idx & 63;
            int n = (c << 5) + nl;
            float x = pts[(((b << 9) + n) << 1) + 0];
            float cd = 8.0f * (float)j + 4.0f;
            float dx = x - cd;
            float d2x = dx * dx;
            float e1x = expf(-d2x * (1.0f/256.0f));
            sEx1q[nl][j] = e1x * e1x;
            sEx2[nl][j]  = expf(-d2x * (1.0f/192.0f));
        }
        // Ey for this block's 16 rows, 32 points
        for (int idx = tid; idx < 512; idx += 256) {
            int nl = idx >> 4, jl = idx & 15;
            int n = (c << 5) + nl;
            int j = iy0 + jl;
            float y = pts[(((b << 9) + n) << 1) + 1];
            float cd = 8.0f * (float)j + 4.0f;
            float dy = y - cd;
            float d2y = dy * dy;
            float e1y = expf(-d2y * (1.0f/256.0f));
            sEy1q[nl][jl] = e1y * e1y;
            sEy2[nl][jl]  = expf(-d2y * (1.0f/192.0f));
        }
        __syncthreads();
#pragma unroll 4
        for (int nl = 0; nl < 32; nl++) {
            float4 ex2 = *(const float4*)&sEx2[nl][ix4];
            float4 ex1 = *(const float4*)&sEx1q[nl][ix4];
            float ey2 = sEy2[nl][iyl];
            float ey1 = sEy1q[nl][iyl];
            accv[0] += ey2 * ex2.x;  accm[0] += ey1 * ex1.x;
            accv[1] += ey2 * ex2.y;  accm[1] += ey1 * ex1.y;
            accv[2] += ey2 * ex2.z;  accm[2] += ey1 * ex1.z;
            accv[3] += ey2 * ex2.w;  accm[3] += ey1 * ex1.w;
        }
    }
#pragma unroll
    for (int q = 0; q < 4; q++) {
        int g = (iy0 + iyl) * 64 + ix4 + q;
        float v = C_V * accv[q] - C_M2 * accm[q];
        g_vraw[b*GG + g] = v;
        out_v[b*GG + g]  = fmaxf(v, 1e-6f);
    }
}

// =====================================================================
// Kernel 2: m[b][n][g] = C_M * Ey1[n][iy] * Ex1[n][ix].  Pure HBM write.
// =====================================================================
__global__ void k_m(const float* __restrict__ pts, float* __restrict__ out_m)
{
    int bn = blockIdx.x, tid = threadIdx.x;
    __shared__ float ex[64], ey[64];
    float x = pts[2*bn], y = pts[2*bn + 1];
    if (tid < 64) {
        float cd = 8.0f * (float)tid + 4.0f;
        float dx = x - cd;
        ex[tid] = expf(-dx*dx * (1.0f/256.0f));
    } else if (tid < 128) {
        int j = tid - 64;
        float cd = 8.0f * (float)j + 4.0f;
        float dy = y - cd;
        ey[j] = expf(-dy*dy * (1.0f/256.0f));
    }
    __syncthreads();
    float4* mrow = (float4*)(out_m + (size_t)bn * GG);
    for (int i = tid; i < 1024; i += 128) {
        int g0 = i << 2;
        int iy = g0 >> 6, ix = g0 & 63;
        float e = C_M * ey[iy];
        mrow[i] = make_float4(e*ex[ix], e*ex[ix+1], e*ex[ix+2], e*ex[ix+3]);
    }
}

// =====================================================================
// Kernel 3: top-100 selection. Bitonic sort of (value desc, idx asc) keys
// == stable argsort(-v); then ascending sort of the 100 indices.
// =====================================================================
__device__ __forceinline__ unsigned int fordu(float f)
{
    unsigned int u = __float_as_uint(f);
    return (u & 0x80000000u) ? ~u : (u | 0x80000000u);
}

__global__ void k_sort(float* __restrict__ out_minds)
{
    int b = blockIdx.x, tid = threadIdx.x;
    __shared__ unsigned long long keys[4096];
    __shared__ unsigned int top[128];
    for (int i = tid; i < 4096; i += 512) {
        float v = g_vraw[b*GG + i];
        keys[i] = ((unsigned long long)(~fordu(v)) << 32) | (unsigned int)i;
    }
    for (int k = 2; k <= 4096; k <<= 1)
        for (int j = k >> 1; j > 0; j >>= 1) {
            __syncthreads();
            for (int i = tid; i < 4096; i += 512) {
                int ixj = i ^ j;
                if (ixj > i) {
                    unsigned long long a = keys[i], c = keys[ixj];
                    bool up = ((i & k) == 0);
                    if ((a > c) == up) { keys[i] = c; keys[ixj] = a; }
                }
            }
        }
    __syncthreads();
    if (tid < 128)
        top[tid] = (tid < 100) ? (unsigned int)(keys[tid] & 0xFFFFFFFFu) : 0xFFFFFFFFu;
    for (int k = 2; k <= 128; k <<= 1)
        for (int j = k >> 1; j > 0; j >>= 1) {
            __syncthreads();
            if (tid < 128) {
                int i = tid, ixj = i ^ j;
                if (ixj > i) {
                    unsigned int a = top[i], c = top[ixj];
                    bool up = ((i & k) == 0);
                    if ((a > c) == up) { top[i] = c; top[ixj] = a; }
                }
            }
        }
    __syncthreads();
    if (tid < 100) {
        int mind = (int)top[tid];
        g_minds[b*MMM + tid] = mind;
        out_minds[b*MMM + tid] = (float)mind;
        float vr = g_vraw[b*GG + mind];
        g_vM[b*MMM + tid] = fmaxf(vr, 1e-6f) + 1e-10f;
    }
}

// =====================================================================
// Kernel 4: gather per (b,n,a): xf, yf, P = disM, mm = tmpm2.
// =====================================================================
__global__ void k_gather(const float* __restrict__ pts)
{
    int b = blockIdx.y, c = blockIdx.x, tid = threadIdx.x;
    __shared__ int sm[100];
    if (tid < 100) sm[tid] = g_minds[b*MMM + tid];
    __syncthreads();
    for (int idx = tid; idx < 64*100; idx += 256) {
        int a = idx % 100, nl = idx / 100;
        int n = (c << 6) + nl;
        int mind = sm[a];
        int iy = mind >> 6, ix = mind & 63;
        float x = pts[(((b << 9) + n) << 1) + 0];
        float y = pts[(((b << 9) + n) << 1) + 1];
        float xf = x - (8.0f*(float)ix + 4.0f);
        float yf = y - (8.0f*(float)iy + 4.0f);
        float P = xf*xf + yf*yf;
        float mm = C_M * expf(-P * (1.0f/256.0f));
        g_xf[b][n][a] = make_float4(xf, yf, P, mm);
    }
}

// =====================================================================
// Kernel 5: A matrix. For i<j: reduce over n using
//   arg1  = (2Q - S)/256,  arg12 = (Q - S)/192,  Smm += mm_i*mm_j
//   A[i][j] = C_M*(C_H*S12 + S1) - Smm ; diag = 1e-10.
// =====================================================================
__global__ void k_pairs(float* __restrict__ out_A)
{
    int b = blockIdx.y, tid = threadIdx.x;
    int p = blockIdx.x * 256 + tid;
    bool active = (p < 4950);
    int i = 0, j = 0;
    if (active) {
        float pf = (float)p;
        i = (int)floorf((199.0f - sqrtf(39601.0f - 8.0f*pf)) * 0.5f);
        if (i < 0) i = 0;
        if (i > 98) i = 98;
        while (i < 98 && (i+1)*(199-(i+1))/2 <= p) i++;
        while (i > 0 && i*(199-i)/2 > p) i--;
        j = i + 1 + (p - i*(199-i)/2);
    }
    __shared__ float4 sx[16][100];
    float a1 = 0.f, a12 = 0.f, amm = 0.f;
    for (int c = 0; c < 32; c++) {
        __syncthreads();
        for (int idx = tid; idx < 1600; idx += 256)
            sx[idx/100][idx%100] = g_xf[b][(c << 4) + idx/100][idx%100];
        __syncthreads();
        if (active) {
#pragma unroll
            for (int nl = 0; nl < 16; nl++) {
                float4 di = sx[nl][i];
                float4 dj = sx[nl][j];
                float Q = di.x*dj.x + di.y*dj.y;
                float S = di.z + dj.z;
                a1  += __expf((2.0f*Q - S) * (1.0f/256.0f));
                a12 += __expf((Q - S) * (1.0f/192.0f));
                amm += di.w * dj.w;
            }
        }
    }
    if (active) {
        float Aij = C_M * (C_H * a12 + a1) - amm;
        out_A[b*10000 + i*100 + j] = Aij;
        out_A[b*10000 + j*100 + i] = Aij;
    }
    if (blockIdx.x == 0 && tid < 100)
        out_A[b*10000 + tid*101] = 1e-10f;
}

// =====================================================================
// Kernel 6: per batch, fp32 in-smem Gauss-Jordan (partial pivoting):
//   invA = inv(A); tmpA = vM_i*invA*vM_j + diag(vM); Bm = inv(tmpA).
// 512 threads; elimination uses a fixed (row-group, column) map with no
// integer division in the hot loop.
// =====================================================================
__global__ void __launch_bounds__(512, 1) k_inv(const float* __restrict__ out_A,
                                                float* __restrict__ out_Bm)
{
    __shared__ float sA[100][101];
    __shared__ float rowk[104];
    __shared__ float colk[104];
    __shared__ float svm[100];
    __shared__ int piv[100];
    __shared__ float redv[4];
    __shared__ int redi[4];
    __shared__ int s_pr;
    __shared__ float s_pinv;

    int b = blockIdx.x, tid = threadIdx.x;
    for (int idx = tid; idx < 10000; idx += 512)
        sA[idx/100][idx%100] = out_A[b*10000 + idx];
    if (tid < 100) svm[tid] = g_vM[b*MMM + tid];

    // fixed element map: thread owns column jj, rows rg, rg+5, ..., rg+95
    int jj = tid % 100;
    int rg = tid / 100;          // 0..5 ; rg==5 -> inactive (tids 500..511)
    bool act = (tid < 500);
    __syncthreads();

    for (int pass = 0; pass < 2; pass++) {
        for (int k = 0; k < 100; k++) {
            // --- partial pivot search on column k, rows [k,100): warps 0..3 ---
            float bv = -1.0f; int br = 0x7FFFFFFF;
            if (tid < 100 - k) { bv = fabsf(sA[k + tid][k]); br = k + tid; }
#pragma unroll
            for (int off = 16; off; off >>= 1) {
                float ov = __shfl_down_sync(0xFFFFFFFFu, bv, off);
                int   oi = __shfl_down_sync(0xFFFFFFFFu, br, off);
                if (ov > bv || (ov == bv && oi < br)) { bv = ov; br = oi; }
            }
            if (tid < 128 && (tid & 31) == 0) { redv[tid >> 5] = bv; redi[tid >> 5] = br; }
            __syncthreads();
            if (tid == 0) {
                float b2 = redv[0]; int r2 = redi[0];
#pragma unroll
                for (int q = 1; q < 4; q++)
                    if (redv[q] > b2 || (redv[q] == b2 && redi[q] < r2)) { b2 = redv[q]; r2 = redi[q]; }
                s_pr = r2; piv[k] = r2;
                s_pinv = 1.0f / sA[r2][k];
            }
            __syncthreads();
            int pr = s_pr;
            float pinv = s_pinv;
            if (pr != k) {
                for (int c = tid; c < 100; c += 512) {
                    float t = sA[k][c]; sA[k][c] = sA[pr][c]; sA[pr][c] = t;
                }
            }
            __syncthreads();
            // scale pivot row (a[k][k] <- pinv), snapshot row; snapshot+zero column
            for (int c = tid; c < 100; c += 512) {
                float val = (c == k) ? pinv : sA[k][c] * pinv;
                sA[k][c] = val; rowk[c] = val;
            }
            for (int r = tid; r < 100; r += 512) {
                if (r != k) { colk[r] = sA[r][k]; sA[r][k] = 0.0f; }
            }
            __syncthreads();
            // eliminate: a[r][j] -= colk[r]*rowk[j]  (j==k yields -f*pinv, correct)
            if (act) {
                float rk = rowk[jj];
#pragma unroll
                for (int t = 0; t < 20; t++) {
                    int rr = rg + t*5;
                    if (rr != k) sA[rr][jj] -= colk[rr] * rk;
                }
            }
            __syncthreads();
        }
        // undo row swaps as column swaps, reverse order
        for (int k = 99; k >= 0; k--) {
            int pp = piv[k];
            if (pp != k) {
                for (int r = tid; r < 100; r += 512) {
                    float t = sA[r][k]; sA[r][k] = sA[r][pp]; sA[r][pp] = t;
                }
            }
            __syncthreads();
        }
        if (pass == 0) {
            // tmpA = vM_i * invA * vM_j + diag(vM)
            for (int idx = tid; idx < 10000; idx += 512) {
                int ii = idx / 100, jc = idx - ii*100;
                float val = svm[ii] * sA[ii][jc] * svm[jc];
                if (ii == jc) val += svm[ii];
                sA[ii][jc] = val;
            }
            __syncthreads();
        }
    }
    for (int idx = tid; idx < 10000; idx += 512)
        out_Bm[b*10000 + idx] = sA[idx/100][idx%100];
}

// =====================================================================
// launch
// =====================================================================
extern "C" void kernel_launch(void* const* d_in, const int* in_sizes, int n_in,
                              void* d_out, int out_size)
{
    const float* pts = (const float*)d_in[0];
    float* out       = (float*)d_out;
    float* out_m     = out;                                   // 8*512*4096
    float* out_v     = out_m + (size_t)NB*NP*GG;              // 8*4096
    float* out_A     = out_v + (size_t)NB*GG;                 // 8*100*100
    float* out_Bm    = out_A + (size_t)NB*MMM*MMM;            // 8*100*100
    float* out_minds = out_Bm + (size_t)NB*MMM*MMM;           // 8*100

    k_mv<<<dim3(4, NB), 256>>>(pts, out_v);
    k_m<<<NB*NP, 128>>>(pts, out_m);
    k_sort<<<NB, 512>>>(out_minds);
    k_gather<<<dim3(8, NB), 256>>>(pts);
    k_pairs<<<dim3(20, NB), 256>>>(out_A);
    k_inv<<<NB, 512>>>(out_A, out_Bm);
}

// round 6
// speedup vs baseline: 4.8857x; 2.3288x over previous
#include <cuda_runtime.h>

// ---------------- problem constants ----------------
#define TWO_PI_D 6.283185307179586
#define C_M  ((float)(1.0/(TWO_PI_D*128.0)))   // 1/(2pi*s1), s1=128 ; also c_g
#define C_H  ((float)(1.0/(TWO_PI_D*96.0)))    // 1/(2pi*s2), s2=96
#define C_V  ((float)((1.0/(TWO_PI_D*96.0))*(1.0/(TWO_PI_D*128.0))))
#define C_M2 ((float)((1.0/(TWO_PI_D*128.0))*(1.0/(TWO_PI_D*128.0))))

#define NB 8      // batch
#define NP 512    // points per image
#define KK 64     // grid per axis
#define GG 4096   // KK*KK
#define MMM 100   // M

// ---------------- scratch (__device__ globals; no allocs allowed) ----------------
__device__ float  g_vraw[NB*GG];
__device__ int    g_minds[NB*MMM];
__device__ float  g_vM[NB*MMM];
__device__ float4 g_xf[NB][NP][MMM];   // (xf, yf, P=xf^2+yf^2, mm=tmpm2)

// =====================================================================
// Kernel 1 (fused): blocks 0..31 compute v (separable reduction, 16
// iy-rows per block, bitwise-identical accumulation chain to R2);
// blocks 32..4127 write m[b][n][g] = C_M*Ey1[iy]*Ex1[ix] (HBM-bound).
// =====================================================================
__global__ void k_mv_m(const float* __restrict__ pts,
                       float* __restrict__ out_v,
                       float* __restrict__ out_m)
{
    int tid = threadIdx.x;
    if (blockIdx.x >= 32) {
        // ---- m part ----
        int bn = blockIdx.x - 32;
        __shared__ float ex[64], ey[64];
        float x = pts[2*bn], y = pts[2*bn + 1];
        if (tid < 64) {
            float cd = 8.0f * (float)tid + 4.0f;
            float dx = x - cd;
            ex[tid] = expf(-dx*dx * (1.0f/256.0f));
        } else if (tid < 128) {
            int j = tid - 64;
            float cd = 8.0f * (float)j + 4.0f;
            float dy = y - cd;
            ey[j] = expf(-dy*dy * (1.0f/256.0f));
        }
        __syncthreads();
        float4* mrow = (float4*)(out_m + (size_t)bn * GG);
        for (int i = tid; i < 1024; i += 256) {
            int g0 = i << 2;
            int iy = g0 >> 6, ix = g0 & 63;
            float e = C_M * ey[iy];
            mrow[i] = make_float4(e*ex[ix], e*ex[ix+1], e*ex[ix+2], e*ex[ix+3]);
        }
        return;
    }
    // ---- v part ----
    int b = blockIdx.x >> 2;
    int iy0 = (blockIdx.x & 3) << 4;     // 16 rows per block
    __shared__ float sEx2[32][64], sEx1q[32][64];
    __shared__ float sEy2[32][16], sEy1q[32][16];
    int ix4 = (tid & 15) << 2;
    int iyl = tid >> 4;
    float accv[4], accm[4];
#pragma unroll
    for (int q = 0; q < 4; q++) { accv[q] = 0.f; accm[q] = 0.f; }

    for (int c = 0; c < 16; c++) {
        __syncthreads();
        for (int idx = tid; idx < 2048; idx += 256) {
            int nl = idx >> 6, j = idx & 63;
            int n = (c << 5) + nl;
            float x = pts[(((b << 9) + n) << 1) + 0];
            float cd = 8.0f * (float)j + 4.0f;
            float dx = x - cd;
            float d2x = dx * dx;
            float e1x = expf(-d2x * (1.0f/256.0f));
            sEx1q[nl][j] = e1x * e1x;
            sEx2[nl][j]  = expf(-d2x * (1.0f/192.0f));
        }
        for (int idx = tid; idx < 512; idx += 256) {
            int nl = idx >> 4, jl = idx & 15;
            int n = (c << 5) + nl;
            int j = iy0 + jl;
            float y = pts[(((b << 9) + n) << 1) + 1];
            float cd = 8.0f * (float)j + 4.0f;
            float dy = y - cd;
            float d2y = dy * dy;
            float e1y = expf(-d2y * (1.0f/256.0f));
            sEy1q[nl][jl] = e1y * e1y;
            sEy2[nl][jl]  = expf(-d2y * (1.0f/192.0f));
        }
        __syncthreads();
#pragma unroll 4
        for (int nl = 0; nl < 32; nl++) {
            float4 ex2 = *(const float4*)&sEx2[nl][ix4];
            float4 ex1 = *(const float4*)&sEx1q[nl][ix4];
            float ey2 = sEy2[nl][iyl];
            float ey1 = sEy1q[nl][iyl];
            accv[0] += ey2 * ex2.x;  accm[0] += ey1 * ex1.x;
            accv[1] += ey2 * ex2.y;  accm[1] += ey1 * ex1.y;
            accv[2] += ey2 * ex2.z;  accm[2] += ey1 * ex1.z;
            accv[3] += ey2 * ex2.w;  accm[3] += ey1 * ex1.w;
        }
    }
#pragma unroll
    for (int q = 0; q < 4; q++) {
        int g = (iy0 + iyl) * 64 + ix4 + q;
        float v = C_V * accv[q] - C_M2 * accm[q];
        g_vraw[b*GG + g] = v;
        out_v[b*GG + g]  = fmaxf(v, 1e-6f);
    }
}

// =====================================================================
// Kernel 3: top-100 selection (stable argsort(-v) via 64-bit keys).
// =====================================================================
__device__ __forceinline__ unsigned int fordu(float f)
{
    unsigned int u = __float_as_uint(f);
    return (u & 0x80000000u) ? ~u : (u | 0x80000000u);
}

__global__ void k_sort(float* __restrict__ out_minds)
{
    int b = blockIdx.x, tid = threadIdx.x;
    __shared__ unsigned long long keys[4096];
    __shared__ unsigned int top[128];
    for (int i = tid; i < 4096; i += 512) {
        float v = g_vraw[b*GG + i];
        keys[i] = ((unsigned long long)(~fordu(v)) << 32) | (unsigned int)i;
    }
    for (int k = 2; k <= 4096; k <<= 1)
        for (int j = k >> 1; j > 0; j >>= 1) {
            __syncthreads();
            for (int i = tid; i < 4096; i += 512) {
                int ixj = i ^ j;
                if (ixj > i) {
                    unsigned long long a = keys[i], c = keys[ixj];
                    bool up = ((i & k) == 0);
                    if ((a > c) == up) { keys[i] = c; keys[ixj] = a; }
                }
            }
        }
    __syncthreads();
    if (tid < 128)
        top[tid] = (tid < 100) ? (unsigned int)(keys[tid] & 0xFFFFFFFFu) : 0xFFFFFFFFu;
    for (int k = 2; k <= 128; k <<= 1)
        for (int j = k >> 1; j > 0; j >>= 1) {
            __syncthreads();
            if (tid < 128) {
                int i = tid, ixj = i ^ j;
                if (ixj > i) {
                    unsigned int a = top[i], c = top[ixj];
                    bool up = ((i & k) == 0);
                    if ((a > c) == up) { top[i] = c; top[ixj] = a; }
                }
            }
        }
    __syncthreads();
    if (tid < 100) {
        int mind = (int)top[tid];
        g_minds[b*MMM + tid] = mind;
        out_minds[b*MMM + tid] = (float)mind;
        float vr = g_vraw[b*GG + mind];
        g_vM[b*MMM + tid] = fmaxf(vr, 1e-6f) + 1e-10f;
    }
}

// =====================================================================
// Kernel 4: gather per (b,n,a): xf, yf, P = disM, mm = tmpm2.
// =====================================================================
__global__ void k_gather(const float* __restrict__ pts)
{
    int b = blockIdx.y, c = blockIdx.x, tid = threadIdx.x;
    __shared__ int sm[100];
    if (tid < 100) sm[tid] = g_minds[b*MMM + tid];
    __syncthreads();
    for (int idx = tid; idx < 64*100; idx += 256) {
        int a = idx % 100, nl = idx / 100;
        int n = (c << 6) + nl;
        int mind = sm[a];
        int iy = mind >> 6, ix = mind & 63;
        float x = pts[(((b << 9) + n) << 1) + 0];
        float y = pts[(((b << 9) + n) << 1) + 1];
        float xf = x - (8.0f*(float)ix + 4.0f);
        float yf = y - (8.0f*(float)iy + 4.0f);
        float P = xf*xf + yf*yf;
        float mm = C_M * expf(-P * (1.0f/256.0f));
        g_xf[b][n][a] = make_float4(xf, yf, P, mm);
    }
}

// =====================================================================
// Kernel 5: A matrix (i<j pairs, reduce over n).
// =====================================================================
__global__ void k_pairs(float* __restrict__ out_A)
{
    int b = blockIdx.y, tid = threadIdx.x;
    int p = blockIdx.x * 256 + tid;
    bool active = (p < 4950);
    int i = 0, j = 0;
    if (active) {
        float pf = (float)p;
        i = (int)floorf((199.0f - sqrtf(39601.0f - 8.0f*pf)) * 0.5f);
        if (i < 0) i = 0;
        if (i > 98) i = 98;
        while (i < 98 && (i+1)*(199-(i+1))/2 <= p) i++;
        while (i > 0 && i*(199-i)/2 > p) i--;
        j = i + 1 + (p - i*(199-i)/2);
    }
    __shared__ float4 sx[16][100];
    float a1 = 0.f, a12 = 0.f, amm = 0.f;
    for (int c = 0; c < 32; c++) {
        __syncthreads();
        for (int idx = tid; idx < 1600; idx += 256)
            sx[idx/100][idx%100] = g_xf[b][(c << 4) + idx/100][idx%100];
        __syncthreads();
        if (active) {
#pragma unroll
            for (int nl = 0; nl < 16; nl++) {
                float4 di = sx[nl][i];
                float4 dj = sx[nl][j];
                float Q = di.x*dj.x + di.y*dj.y;
                float S = di.z + dj.z;
                a1  += __expf((2.0f*Q - S) * (1.0f/256.0f));
                a12 += __expf((Q - S) * (1.0f/192.0f));
                amm += di.w * dj.w;
            }
        }
    }
    if (active) {
        float Aij = C_M * (C_H * a12 + a1) - amm;
        out_A[b*10000 + i*100 + j] = Aij;
        out_A[b*10000 + j*100 + i] = Aij;
    }
    if (blockIdx.x == 0 && tid < 100)
        out_A[b*10000 + tid*101] = 1e-10f;
}

// =====================================================================
// Kernel 6: Bm = diag(1/vM) - inv(A + diag(vM)).
//   (Identity: tmpA = D·invA·D + D = D·invA·(A+D)  =>  Bm = D^-1 - (A+D)^-1)
// Single fp32 in-smem Gauss-Jordan with partial pivoting, 3 barriers/step:
//   [warp-0 pivot search] [fused swap+scale+snapshot+zero] [eliminate]
// Row-swap undo folded into a final column-permutation gather.
// =====================================================================
__global__ void __launch_bounds__(512, 1) k_inv(const float* __restrict__ out_A,
                                                float* __restrict__ out_Bm)
{
    __shared__ float sA[100][101];
    __shared__ float rowk[104];
    __shared__ float colk[104];
    __shared__ float svm[100];
    __shared__ int piv[100];
    __shared__ int cperm[100];
    __shared__ int s_pr;
    __shared__ float s_pinv;

    int b = blockIdx.x, tid = threadIdx.x;
    if (tid < 100) svm[tid] = g_vM[b*MMM + tid];
    __syncthreads();
    // E = A + diag(vM)  (A diag is 1e-10 -> E_ii = 1e-10 + vM_i)
    for (int idx = tid; idx < 10000; idx += 512) {
        int ii = idx / 100, jc = idx - ii*100;
        float val = out_A[b*10000 + idx];
        if (ii == jc) val += svm[ii];
        sA[ii][jc] = val;
    }

    int jj = tid % 100;
    int rg = tid / 100;          // 0..5 ; tids 500..511 inactive in elimination
    bool act = (tid < 500);
    __syncthreads();

    for (int k = 0; k < 100; k++) {
        // --- Phase A: warp 0 pivot search on column k, rows [k,100) ---
        if (tid < 32) {
            float bv = -1.0f; int br = 0x7FFFFFFF;
#pragma unroll
            for (int q = 0; q < 4; q++) {
                int r = k + tid + (q << 5);
                if (r < 100) {
                    float av = fabsf(sA[r][k]);
                    if (av > bv) { bv = av; br = r; }   // ascending r: ties keep first
                }
            }
#pragma unroll
            for (int off = 16; off; off >>= 1) {
                float ov = __shfl_down_sync(0xFFFFFFFFu, bv, off);
                int   oi = __shfl_down_sync(0xFFFFFFFFu, br, off);
                if (ov > bv || (ov == bv && oi < br)) { bv = ov; br = oi; }
            }
            if (tid == 0) {
                s_pr = br; piv[k] = br;
                s_pinv = 1.0f / sA[br][k];
            }
        }
        __syncthreads();
        int pr = s_pr;
        float pinv = s_pinv;
        // --- Phase B: fused swap(k,pr) + scale row k + snapshots + zero col k ---
        if (tid < 100) {
            int c = tid;
            float told_k = sA[k][c];
            float told_p = sA[pr][c];                 // == told_k if pr==k
            float rv = (c == k) ? pinv : told_p * pinv;
            rowk[c] = rv;
            sA[k][c] = rv;
            if (pr != k) {
                if (c == k) { colk[pr] = told_k; sA[pr][k] = 0.0f; }
                else        { sA[pr][c] = told_k; }
            }
        } else if (tid >= 256 && tid < 356) {
            int r = tid - 256;
            if (r != k && r != pr) {
                colk[r] = sA[r][k];
                sA[r][k] = 0.0f;
            }
        }
        __syncthreads();
        // --- Phase C: eliminate (j==k yields -f*pinv via zeroed column) ---
        if (act) {
            float rk = rowk[jj];
#pragma unroll
            for (int t = 0; t < 20; t++) {
                int rr = rg + t*5;
                if (rr != k) sA[rr][jj] -= colk[rr] * rk;
            }
        }
        __syncthreads();
    }
    // column permutation from reversed row swaps: c=id; for k=99..0 swap(c[k],c[piv[k]])
    if (tid == 0) {
        for (int j2 = 0; j2 < 100; j2++) cperm[j2] = j2;
        for (int k = 99; k >= 0; k--) {
            int pp = piv[k];
            int t = cperm[k]; cperm[k] = cperm[pp]; cperm[pp] = t;
        }
    }
    __syncthreads();
    // Bm = diag(1/vM) - W  (W = permuted-inverse gather)
    for (int idx = tid; idx < 10000; idx += 512) {
        int ii = idx / 100, jc = idx - ii*100;
        float w = sA[ii][cperm[jc]];
        float d = (ii == jc) ? (1.0f / svm[ii]) : 0.0f;
        out_Bm[b*10000 + idx] = d - w;
    }
}

// =====================================================================
// launch
// =====================================================================
extern "C" void kernel_launch(void* const* d_in, const int* in_sizes, int n_in,
                              void* d_out, int out_size)
{
    const float* pts = (const float*)d_in[0];
    float* out       = (float*)d_out;
    float* out_m     = out;                                   // 8*512*4096
    float* out_v     = out_m + (size_t)NB*NP*GG;              // 8*4096
    float* out_A     = out_v + (size_t)NB*GG;                 // 8*100*100
    float* out_Bm    = out_A + (size_t)NB*MMM*MMM;            // 8*100*100
    float* out_minds = out_Bm + (size_t)NB*MMM*MMM;           // 8*100

    k_mv_m<<<32 + NB*NP, 256>>>(pts, out_v, out_m);
    k_sort<<<NB, 512>>>(out_minds);
    k_gather<<<dim3(8, NB), 256>>>(pts);
    k_pairs<<<dim3(20, NB), 256>>>(out_A);
    k_inv<<<NB, 512>>>(out_A, out_Bm);
}

// round 8
// speedup vs baseline: 5.7786x; 1.1828x over previous
#include <cuda_runtime.h>

// ---------------- problem constants ----------------
#define TWO_PI_D 6.283185307179586
#define C_M  ((float)(1.0/(TWO_PI_D*128.0)))   // 1/(2pi*s1), s1=128 ; also c_g
#define C_H  ((float)(1.0/(TWO_PI_D*96.0)))    // 1/(2pi*s2), s2=96
#define C_V  ((float)((1.0/(TWO_PI_D*96.0))*(1.0/(TWO_PI_D*128.0))))
#define C_M2 ((float)((1.0/(TWO_PI_D*128.0))*(1.0/(TWO_PI_D*128.0))))

#define NB 8      // batch
#define NP 512    // points per image
#define KK 64     // grid per axis
#define GG 4096   // KK*KK
#define MMM 100   // M
#define NCH 8     // n-chunks for pair reduction

// ---------------- scratch (__device__ globals; no allocs allowed) ----------------
__device__ float  g_vraw[NB*GG];
__device__ int    g_minds[NB*MMM];
__device__ float  g_vM[NB*MMM];
__device__ float4 g_xf[NB][NP][MMM];      // (xf, yf, P=xf^2+yf^2, mm=tmpm2)
__device__ float4 g_part[NB][NCH][4960];  // per-chunk partial (a1, a12, amm, -)

// =====================================================================
// Kernel 1 (fused): blocks 0..31 compute v (separable reduction, 16
// iy-rows per block); blocks 32..4127 write m = C_M*Ey1*Ex1 (HBM-bound).
// =====================================================================
__global__ void k_mv_m(const float* __restrict__ pts,
                       float* __restrict__ out_v,
                       float* __restrict__ out_m)
{
    int tid = threadIdx.x;
    if (blockIdx.x >= 32) {
        // ---- m part ----
        int bn = blockIdx.x - 32;
        __shared__ float ex[64], ey[64];
        float x = pts[2*bn], y = pts[2*bn + 1];
        if (tid < 64) {
            float cd = 8.0f * (float)tid + 4.0f;
            float dx = x - cd;
            ex[tid] = expf(-dx*dx * (1.0f/256.0f));
        } else if (tid < 128) {
            int j = tid - 64;
            float cd = 8.0f * (float)j + 4.0f;
            float dy = y - cd;
            ey[j] = expf(-dy*dy * (1.0f/256.0f));
        }
        __syncthreads();
        float4* mrow = (float4*)(out_m + (size_t)bn * GG);
        for (int i = tid; i < 1024; i += 256) {
            int g0 = i << 2;
            int iy = g0 >> 6, ix = g0 & 63;
            float e = C_M * ey[iy];
            mrow[i] = make_float4(e*ex[ix], e*ex[ix+1], e*ex[ix+2], e*ex[ix+3]);
        }
        return;
    }
    // ---- v part ----
    int b = blockIdx.x >> 2;
    int iy0 = (blockIdx.x & 3) << 4;     // 16 rows per block
    __shared__ float sEx2[32][64], sEx1q[32][64];
    __shared__ float sEy2[32][16], sEy1q[32][16];
    int ix4 = (tid & 15) << 2;
    int iyl = tid >> 4;
    float accv[4], accm[4];
#pragma unroll
    for (int q = 0; q < 4; q++) { accv[q] = 0.f; accm[q] = 0.f; }

    for (int c = 0; c < 16; c++) {
        __syncthreads();
        for (int idx = tid; idx < 2048; idx += 256) {
            int nl = idx >> 6, j = idx & 63;
            int n = (c << 5) + nl;
            float x = pts[(((b << 9) + n) << 1) + 0];
            float cd = 8.0f * (float)j + 4.0f;
            float dx = x - cd;
            float d2x = dx * dx;
            float e1x = expf(-d2x * (1.0f/256.0f));
            sEx1q[nl][j] = e1x * e1x;
            sEx2[nl][j]  = expf(-d2x * (1.0f/192.0f));
        }
        for (int idx = tid; idx < 512; idx += 256) {
            int nl = idx >> 4, jl = idx & 15;
            int n = (c << 5) + nl;
            int j = iy0 + jl;
            float y = pts[(((b << 9) + n) << 1) + 1];
            float cd = 8.0f * (float)j + 4.0f;
            float dy = y - cd;
            float d2y = dy * dy;
            float e1y = expf(-d2y * (1.0f/256.0f));
            sEy1q[nl][jl] = e1y * e1y;
            sEy2[nl][jl]  = expf(-d2y * (1.0f/192.0f));
        }
        __syncthreads();
#pragma unroll 4
        for (int nl = 0; nl < 32; nl++) {
            float4 ex2 = *(const float4*)&sEx2[nl][ix4];
            float4 ex1 = *(const float4*)&sEx1q[nl][ix4];
            float ey2 = sEy2[nl][iyl];
            float ey1 = sEy1q[nl][iyl];
            accv[0] += ey2 * ex2.x;  accm[0] += ey1 * ex1.x;
            accv[1] += ey2 * ex2.y;  accm[1] += ey1 * ex1.y;
            accv[2] += ey2 * ex2.z;  accm[2] += ey1 * ex1.z;
            accv[3] += ey2 * ex2.w;  accm[3] += ey1 * ex1.w;
        }
    }
#pragma unroll
    for (int q = 0; q < 4; q++) {
        int g = (iy0 + iyl) * 64 + ix4 + q;
        float v = C_V * accv[q] - C_M2 * accm[q];
        g_vraw[b*GG + g] = v;
        out_v[b*GG + g]  = fmaxf(v, 1e-6f);
    }
}

// =====================================================================
// Kernel 3: top-100 selection (stable argsort(-v) via 64-bit keys).
// =====================================================================
__device__ __forceinline__ unsigned int fordu(float f)
{
    unsigned int u = __float_as_uint(f);
    return (u & 0x80000000u) ? ~u : (u | 0x80000000u);
}

__global__ void k_sort(float* __restrict__ out_minds)
{
    int b = blockIdx.x, tid = threadIdx.x;
    __shared__ unsigned long long keys[4096];
    __shared__ unsigned int top[128];
    for (int i = tid; i < 4096; i += 512) {
        float v = g_vraw[b*GG + i];
        keys[i] = ((unsigned long long)(~fordu(v)) << 32) | (unsigned int)i;
    }
    for (int k = 2; k <= 4096; k <<= 1)
        for (int j = k >> 1; j > 0; j >>= 1) {
            __syncthreads();
            for (int i = tid; i < 4096; i += 512) {
                int ixj = i ^ j;
                if (ixj > i) {
                    unsigned long long a = keys[i], c = keys[ixj];
                    bool up = ((i & k) == 0);
                    if ((a > c) == up) { keys[i] = c; keys[ixj] = a; }
                }
            }
        }
    __syncthreads();
    if (tid < 128)
        top[tid] = (tid < 100) ? (unsigned int)(keys[tid] & 0xFFFFFFFFu) : 0xFFFFFFFFu;
    for (int k = 2; k <= 128; k <<= 1)
        for (int j = k >> 1; j > 0; j >>= 1) {
            __syncthreads();
            if (tid < 128) {
                int i = tid, ixj = i ^ j;
                if (ixj > i) {
                    unsigned int a = top[i], c = top[ixj];
                    bool up = ((i & k) == 0);
                    if ((a > c) == up) { top[i] = c; top[ixj] = a; }
                }
            }
        }
    __syncthreads();
    if (tid < 100) {
        int mind = (int)top[tid];
        g_minds[b*MMM + tid] = mind;
        out_minds[b*MMM + tid] = (float)mind;
        float vr = g_vraw[b*GG + mind];
        g_vM[b*MMM + tid] = fmaxf(vr, 1e-6f) + 1e-10f;
    }
}

// =====================================================================
// Kernel 4: gather per (b,n,a): xf, yf, P = disM, mm = tmpm2.
// 32 blocks per batch (16 n each) for occupancy.
// =====================================================================
__global__ void k_gather(const float* __restrict__ pts)
{
    int b = blockIdx.y, c = blockIdx.x, tid = threadIdx.x;
    __shared__ int sm[100];
    if (tid < 100) sm[tid] = g_minds[b*MMM + tid];
    __syncthreads();
    for (int idx = tid; idx < 16*100; idx += 256) {
        int a = idx % 100, nl = idx / 100;
        int n = (c << 4) + nl;
        int mind = sm[a];
        int iy = mind >> 6, ix = mind & 63;
        float x = pts[(((b << 9) + n) << 1) + 0];
        float y = pts[(((b << 9) + n) << 1) + 1];
        float xf = x - (8.0f*(float)ix + 4.0f);
        float yf = y - (8.0f*(float)iy + 4.0f);
        float P = xf*xf + yf*yf;
        float mm = C_M * expf(-P * (1.0f/256.0f));
        g_xf[b][n][a] = make_float4(xf, yf, P, mm);
    }
}

// =====================================================================
// pair index map p -> (i<j), row-major upper triangle
// =====================================================================
__device__ __forceinline__ void pair_ij(int p, int& i, int& j)
{
    float pf = (float)p;
    i = (int)floorf((199.0f - sqrtf(39601.0f - 8.0f*pf)) * 0.5f);
    if (i < 0) i = 0;
    if (i > 98) i = 98;
    while (i < 98 && (i+1)*(199-(i+1))/2 <= p) i++;
    while (i > 0 && i*(199-i)/2 > p) i--;
    j = i + 1 + (p - i*(199-i)/2);
}

// =====================================================================
// Kernel 5a: pair partials over a 64-n chunk.  grid (20, NCH, NB).
// =====================================================================
__global__ void k_pairs1(void)
{
    int b = blockIdx.z, nc = blockIdx.y, tid = threadIdx.x;
    int p = blockIdx.x * 256 + tid;
    bool active = (p < 4950);
    int i = 0, j = 0;
    if (active) pair_ij(p, i, j);

    __shared__ float4 sx[16][100];
    float a1 = 0.f, a12 = 0.f, amm = 0.f;
    for (int c = 0; c < 4; c++) {
        int n0 = (nc << 6) + (c << 4);
        __syncthreads();
        for (int idx = tid; idx < 1600; idx += 256)
            sx[idx/100][idx%100] = g_xf[b][n0 + idx/100][idx%100];
        __syncthreads();
        if (active) {
#pragma unroll
            for (int nl = 0; nl < 16; nl++) {
                float4 di = sx[nl][i];
                float4 dj = sx[nl][j];
                float Q = di.x*dj.x + di.y*dj.y;
                float S = di.z + dj.z;
                a1  += __expf((2.0f*Q - S) * (1.0f/256.0f));
                a12 += __expf((Q - S) * (1.0f/192.0f));
                amm += di.w * dj.w;
            }
        }
    }
    if (active) g_part[b][nc][p] = make_float4(a1, a12, amm, 0.f);
}

// =====================================================================
// Kernel 5b: reduce chunk partials (fixed order: deterministic), write A.
// =====================================================================
__global__ void k_pairs2(float* __restrict__ out_A)
{
    int b = blockIdx.y, tid = threadIdx.x;
    int p = blockIdx.x * 256 + tid;
    if (p < 4950) {
        int i, j;
        pair_ij(p, i, j);
        float a1 = 0.f, a12 = 0.f, amm = 0.f;
#pragma unroll
        for (int nc = 0; nc < NCH; nc++) {
            float4 q = g_part[b][nc][p];
            a1 += q.x; a12 += q.y; amm += q.z;
        }
        float Aij = C_M * (C_H * a12 + a1) - amm;
        out_A[b*10000 + i*100 + j] = Aij;
        out_A[b*10000 + j*100 + i] = Aij;
    }
    if (blockIdx.x == 0 && tid < 100)
        out_A[b*10000 + tid*101] = 1e-10f;
}

// =====================================================================
// Kernel 6: Bm = diag(1/vM) - inv(A + diag(vM)).
// fp32 in-smem Gauss-Jordan, partial pivoting, 3 barriers/step.
// =====================================================================
__global__ void __launch_bounds__(512, 1) k_inv(const float* __restrict__ out_A,
                                                float* __restrict__ out_Bm)
{
    __shared__ float sA[100][101];
    __shared__ float rowk[104];
    __shared__ float colk[104];
    __shared__ float svm[100];
    __shared__ int piv[100];
    __shared__ int cperm[100];
    __shared__ int s_pr;
    __shared__ float s_pinv;

    int b = blockIdx.x, tid = threadIdx.x;
    if (tid < 100) svm[tid] = g_vM[b*MMM + tid];
    __syncthreads();
    for (int idx = tid; idx < 10000; idx += 512) {
        int ii = idx / 100, jc = idx - ii*100;
        float val = out_A[b*10000 + idx];
        if (ii == jc) val += svm[ii];
        sA[ii][jc] = val;
    }

    int jj = tid % 100;
    int rg = tid / 100;
    bool act = (tid < 500);
    __syncthreads();

    for (int k = 0; k < 100; k++) {
        if (tid < 32) {
            float bv = -1.0f; int br = 0x7FFFFFFF;
#pragma unroll
            for (int q = 0; q < 4; q++) {
                int r = k + tid + (q << 5);
                if (r < 100) {
                    float av = fabsf(sA[r][k]);
                    if (av > bv) { bv = av; br = r; }
                }
            }
#pragma unroll
            for (int off = 16; off; off >>= 1) {
                float ov = __shfl_down_sync(0xFFFFFFFFu, bv, off);
                int   oi = __shfl_down_sync(0xFFFFFFFFu, br, off);
                if (ov > bv || (ov == bv && oi < br)) { bv = ov; br = oi; }
            }
            if (tid == 0) {
                s_pr = br; piv[k] = br;
                s_pinv = 1.0f / sA[br][k];
            }
        }
        __syncthreads();
        int pr = s_pr;
        float pinv = s_pinv;
        if (tid < 100) {
            int c = tid;
            float told_k = sA[k][c];
            float told_p = sA[pr][c];
            float rv = (c == k) ? pinv : told_p * pinv;
            rowk[c] = rv;
            sA[k][c] = rv;
            if (pr != k) {
                if (c == k) { colk[pr] = told_k; sA[pr][k] = 0.0f; }
                else        { sA[pr][c] = told_k; }
            }
        } else if (tid >= 256 && tid < 356) {
            int r = tid - 256;
            if (r != k && r != pr) {
                colk[r] = sA[r][k];
                sA[r][k] = 0.0f;
            }
        }
        __syncthreads();
        if (act) {
            float rk = rowk[jj];
#pragma unroll
            for (int t = 0; t < 20; t++) {
                int rr = rg + t*5;
                if (rr != k) sA[rr][jj] -= colk[rr] * rk;
            }
        }
        __syncthreads();
    }
    if (tid == 0) {
        for (int j2 = 0; j2 < 100; j2++) cperm[j2] = j2;
        for (int k = 99; k >= 0; k--) {
            int pp = piv[k];
            int t = cperm[k]; cperm[k] = cperm[pp]; cperm[pp] = t;
        }
    }
    __syncthreads();
    for (int idx = tid; idx < 10000; idx += 512) {
        int ii = idx / 100, jc = idx - ii*100;
        float w = sA[ii][cperm[jc]];
        float d = (ii == jc) ? (1.0f / svm[ii]) : 0.0f;
        out_Bm[b*10000 + idx] = d - w;
    }
}

// =====================================================================
// launch
// =====================================================================
extern "C" void kernel_launch(void* const* d_in, const int* in_sizes, int n_in,
                              void* d_out, int out_size)
{
    const float* pts = (const float*)d_in[0];
    float* out       = (float*)d_out;
    float* out_m     = out;                                   // 8*512*4096
    float* out_v     = out_m + (size_t)NB*NP*GG;              // 8*4096
    float* out_A     = out_v + (size_t)NB*GG;                 // 8*100*100
    float* out_Bm    = out_A + (size_t)NB*MMM*MMM;            // 8*100*100
    float* out_minds = out_Bm + (size_t)NB*MMM*MMM;           // 8*100

    k_mv_m<<<32 + NB*NP, 256>>>(pts, out_v, out_m);
    k_sort<<<NB, 512>>>(out_minds);
    k_gather<<<dim3(32, NB), 256>>>(pts);
    k_pairs1<<<dim3(20, NCH, NB), 256>>>();
    k_pairs2<<<dim3(20, NB), 256>>>(out_A);
    k_inv<<<NB, 512>>>(out_A, out_Bm);
}

// round 12
// speedup vs baseline: 5.8976x; 1.0206x over previous
#include <cuda_runtime.h>

// ---------------- problem constants ----------------
#define TWO_PI_D 6.283185307179586
#define C_M  ((float)(1.0/(TWO_PI_D*128.0)))   // 1/(2pi*s1), s1=128 ; also c_g
#define C_H  ((float)(1.0/(TWO_PI_D*96.0)))    // 1/(2pi*s2), s2=96
#define C_V  ((float)((1.0/(TWO_PI_D*96.0))*(1.0/(TWO_PI_D*128.0))))
#define C_M2 ((float)((1.0/(TWO_PI_D*128.0))*(1.0/(TWO_PI_D*128.0))))

#define NB 8      // batch
#define NP 512    // points per image
#define KK 64     // grid per axis
#define GG 4096   // KK*KK
#define MMM 100   // M

// ---------------- scratch (__device__ globals; no allocs allowed) ----------------
__device__ float  g_vraw[NB*GG];
__device__ int    g_minds[NB*MMM];
__device__ float  g_vM[NB*MMM];
// midpoint exp tables: s (or t) in 0..126, padded to 128
__device__ float  g_Ex192[NB][NP][128];   // exp(-(x-(4s+4))^2/192)
__device__ float  g_Ex128[NB][NP][128];   // exp(-(x-(4s+4))^2/128)
__device__ float  g_Ey192[NB][NP][128];
__device__ float  g_Ey128[NB][NP][128];
// pair tables T[t][s], U[t][s]
__device__ float  g_T[NB][128][128];
__device__ float  g_U[NB][128][128];

// =====================================================================
// L1: blocks 0..31 compute v (bitwise-identical accumulation chain);
// blocks 32..4127: midpoint exp tables per (b, n)  (A path, __expf ok).
// =====================================================================
__global__ void k_v_emid(const float* __restrict__ pts,
                         float* __restrict__ out_v)
{
    int tid = threadIdx.x;
    if (blockIdx.x >= 32) {
        int u = blockIdx.x - 32;            // 0..4095
        int b = u >> 9, n = u & 511;
        float x = pts[2*u], y = pts[2*u + 1];
        if (tid < 128) {
            int s = tid;
            if (s < 127) {
                float d = x - (4.0f*(float)s + 4.0f);
                float d2 = d * d;
                g_Ex192[b][n][s] = __expf(-d2 * (1.0f/192.0f));
                g_Ex128[b][n][s] = __expf(-d2 * (1.0f/128.0f));
            } else {
                g_Ex192[b][n][127] = 0.0f;
                g_Ex128[b][n][127] = 0.0f;
            }
        } else {
            int s = tid - 128;
            if (s < 127) {
                float d = y - (4.0f*(float)s + 4.0f);
                float d2 = d * d;
                g_Ey192[b][n][s] = __expf(-d2 * (1.0f/192.0f));
                g_Ey128[b][n][s] = __expf(-d2 * (1.0f/128.0f));
            } else if (s == 127) {
                g_Ey192[b][n][127] = 0.0f;
                g_Ey128[b][n][127] = 0.0f;
            }
        }
        return;
    }
    // ---- v part (unchanged, bitwise) ----
    int b = blockIdx.x >> 2;
    int iy0 = (blockIdx.x & 3) << 4;
    __shared__ float sEx2[32][64], sEx1q[32][64];
    __shared__ float sEy2[32][16], sEy1q[32][16];
    int ix4 = (tid & 15) << 2;
    int iyl = tid >> 4;
    float accv[4], accm[4];
#pragma unroll
    for (int q = 0; q < 4; q++) { accv[q] = 0.f; accm[q] = 0.f; }

    for (int c = 0; c < 16; c++) {
        __syncthreads();
        for (int idx = tid; idx < 2048; idx += 256) {
            int nl = idx >> 6, j = idx & 63;
            int n = (c << 5) + nl;
            float x = pts[(((b << 9) + n) << 1) + 0];
            float cd = 8.0f * (float)j + 4.0f;
            float dx = x - cd;
            float d2x = dx * dx;
            float e1x = expf(-d2x * (1.0f/256.0f));
            sEx1q[nl][j] = e1x * e1x;
            sEx2[nl][j]  = expf(-d2x * (1.0f/192.0f));
        }
        for (int idx = tid; idx < 512; idx += 256) {
            int nl = idx >> 4, jl = idx & 15;
            int n = (c << 5) + nl;
            int j = iy0 + jl;
            float y = pts[(((b << 9) + n) << 1) + 1];
            float cd = 8.0f * (float)j + 4.0f;
            float dy = y - cd;
            float d2y = dy * dy;
            float e1y = expf(-d2y * (1.0f/256.0f));
            sEy1q[nl][jl] = e1y * e1y;
            sEy2[nl][jl]  = expf(-d2y * (1.0f/192.0f));
        }
        __syncthreads();
#pragma unroll 4
        for (int nl = 0; nl < 32; nl++) {
            float4 ex2 = *(const float4*)&sEx2[nl][ix4];
            float4 ex1 = *(const float4*)&sEx1q[nl][ix4];
            float ey2 = sEy2[nl][iyl];
            float ey1 = sEy1q[nl][iyl];
            accv[0] += ey2 * ex2.x;  accm[0] += ey1 * ex1.x;
            accv[1] += ey2 * ex2.y;  accm[1] += ey1 * ex1.y;
            accv[2] += ey2 * ex2.z;  accm[2] += ey1 * ex1.z;
            accv[3] += ey2 * ex2.w;  accm[3] += ey1 * ex1.w;
        }
    }
#pragma unroll
    for (int q = 0; q < 4; q++) {
        int g = (iy0 + iyl) * 64 + ix4 + q;
        float v = C_V * accv[q] - C_M2 * accm[q];
        g_vraw[b*GG + g] = v;
        out_v[b*GG + g]  = fmaxf(v, 1e-6f);
    }
}

// =====================================================================
// L2: heterogeneous launch.
//   blocks 0..7       : top-100 selection (stable argsort(-v))
//   blocks 8..135     : T/U table reductions (16 per batch, 8 t-rows each)
//   blocks 136..4231  : m = C_M*Ey1*Ex1  (HBM-bound write)
// =====================================================================
__device__ __forceinline__ unsigned int fordu(float f)
{
    unsigned int u = __float_as_uint(f);
    return (u & 0x80000000u) ? ~u : (u | 0x80000000u);
}

union SmemL2 {
    struct { unsigned long long keys[4096]; unsigned int top[128]; } s;
    struct { float tx[32][128], ux[32][128]; float ty[32][8], uy[32][8]; } t;
    struct { float ex[64], ey[64]; } m;
};

__global__ void k_sort_tab_m(const float* __restrict__ pts,
                             float* __restrict__ out_minds,
                             float* __restrict__ out_m)
{
    __shared__ SmemL2 u;
    int tid = threadIdx.x;
    int bx = blockIdx.x;

    if (bx >= 136) {
        // ---- m part ----
        int bn = bx - 136;
        float x = pts[2*bn], y = pts[2*bn + 1];
        if (tid < 64) {
            float cd = 8.0f * (float)tid + 4.0f;
            float dx = x - cd;
            u.m.ex[tid] = expf(-dx*dx * (1.0f/256.0f));
        } else if (tid < 128) {
            int j = tid - 64;
            float cd = 8.0f * (float)j + 4.0f;
            float dy = y - cd;
            u.m.ey[j] = expf(-dy*dy * (1.0f/256.0f));
        }
        __syncthreads();
        float4* mrow = (float4*)(out_m + (size_t)bn * GG);
        for (int i = tid; i < 1024; i += 256) {
            int g0 = i << 2;
            int iy = g0 >> 6, ix = g0 & 63;
            float e = C_M * u.m.ey[iy];
            mrow[i] = make_float4(e*u.m.ex[ix], e*u.m.ex[ix+1], e*u.m.ex[ix+2], e*u.m.ex[ix+3]);
        }
        return;
    }
    if (bx >= 8) {
        // ---- T/U table part: T[t][s] = sum_n Ey192[t]*Ex192[s]; U likewise ----
        int u2 = bx - 8;
        int b = u2 >> 4;
        int t00 = (u2 & 15) << 3;            // 8 t-rows per block
        int ox = (tid & 31) << 2;            // 4 s per thread
        int oyp = tid >> 5;                  // active threads: 0..3 (2 rows each)
        bool act = (tid < 128);
        float accT[2][4], accU[2][4];
#pragma unroll
        for (int r = 0; r < 2; r++)
#pragma unroll
            for (int q = 0; q < 4; q++) { accT[r][q] = 0.f; accU[r][q] = 0.f; }

        for (int c = 0; c < 16; c++) {
            int n0 = c << 5;
            __syncthreads();
            const float4* px = (const float4*)&g_Ex192[b][n0][0];
            const float4* pu = (const float4*)&g_Ex128[b][n0][0];
            for (int idx = tid; idx < 1024; idx += 256) {
                ((float4*)u.t.tx)[idx] = px[idx];
                ((float4*)u.t.ux)[idx] = pu[idx];
            }
            {
                int idx = tid;
                if (idx < 256) {
                    int nl = idx >> 3, yy = idx & 7;
                    u.t.ty[nl][yy] = g_Ey192[b][n0 + nl][t00 + yy];
                    u.t.uy[nl][yy] = g_Ey128[b][n0 + nl][t00 + yy];
                }
            }
            __syncthreads();
            if (act) {
#pragma unroll 4
                for (int nl = 0; nl < 32; nl++) {
                    float4 tx = *(const float4*)&u.t.tx[nl][ox];
                    float4 ux = *(const float4*)&u.t.ux[nl][ox];
                    float ty0 = u.t.ty[nl][2*oyp], ty1 = u.t.ty[nl][2*oyp+1];
                    float uy0 = u.t.uy[nl][2*oyp], uy1 = u.t.uy[nl][2*oyp+1];
                    accT[0][0] += ty0*tx.x; accT[0][1] += ty0*tx.y; accT[0][2] += ty0*tx.z; accT[0][3] += ty0*tx.w;
                    accT[1][0] += ty1*tx.x; accT[1][1] += ty1*tx.y; accT[1][2] += ty1*tx.z; accT[1][3] += ty1*tx.w;
                    accU[0][0] += uy0*ux.x; accU[0][1] += uy0*ux.y; accU[0][2] += uy0*ux.z; accU[0][3] += uy0*ux.w;
                    accU[1][0] += uy1*ux.x; accU[1][1] += uy1*ux.y; accU[1][2] += uy1*ux.z; accU[1][3] += uy1*ux.w;
                }
            }
        }
        if (act) {
#pragma unroll
            for (int r = 0; r < 2; r++) {
                int t = t00 + 2*oyp + r;
                *(float4*)&g_T[b][t][ox] = make_float4(accT[r][0], accT[r][1], accT[r][2], accT[r][3]);
                *(float4*)&g_U[b][t][ox] = make_float4(accU[r][0], accU[r][1], accU[r][2], accU[r][3]);
            }
        }
        return;
    }
    // ---- sort part ----
    int b = bx;
    for (int i = tid; i < 4096; i += 256) {
        float v = g_vraw[b*GG + i];
        u.s.keys[i] = ((unsigned long long)(~fordu(v)) << 32) | (unsigned int)i;
    }
    for (int k = 2; k <= 4096; k <<= 1)
        for (int j = k >> 1; j > 0; j >>= 1) {
            __syncthreads();
            for (int i = tid; i < 4096; i += 256) {
                int ixj = i ^ j;
                if (ixj > i) {
                    unsigned long long a = u.s.keys[i], c = u.s.keys[ixj];
                    bool up = ((i & k) == 0);
                    if ((a > c) == up) { u.s.keys[i] = c; u.s.keys[ixj] = a; }
                }
            }
        }
    __syncthreads();
    if (tid < 128)
        u.s.top[tid] = (tid < 100) ? (unsigned int)(u.s.keys[tid] & 0xFFFFFFFFu) : 0xFFFFFFFFu;
    for (int k = 2; k <= 128; k <<= 1)
        for (int j = k >> 1; j > 0; j >>= 1) {
            __syncthreads();
            if (tid < 128) {
                int i = tid, ixj = i ^ j;
                if (ixj > i) {
                    unsigned int a = u.s.top[i], c = u.s.top[ixj];
                    bool up = ((i & k) == 0);
                    if ((a > c) == up) { u.s.top[i] = c; u.s.top[ixj] = a; }
                }
            }
        }
    __syncthreads();
    if (tid < 100) {
        int mind = (int)u.s.top[tid];
        g_minds[b*MMM + tid] = mind;
        out_minds[b*MMM + tid] = (float)mind;
        float vr = g_vraw[b*GG + mind];
        g_vM[b*MMM + tid] = fmaxf(vr, 1e-6f) + 1e-10f;
    }
}

// =====================================================================
// pair index map p -> (i<j), row-major upper triangle
// =====================================================================
__device__ __forceinline__ void pair_ij(int p, int& i, int& j)
{
    float pf = (float)p;
    i = (int)floorf((199.0f - sqrtf(39601.0f - 8.0f*pf)) * 0.5f);
    if (i < 0) i = 0;
    if (i > 98) i = 98;
    while (i < 98 && (i+1)*(199-(i+1))/2 <= p) i++;
    while (i > 0 && i*(199-i)/2 > p) i--;
    j = i + 1 + (p - i*(199-i)/2);
}

// =====================================================================
// L3: A assembly from tables.
//   A_ij = C_M*e^{-df/256}*(C_H*T[t][s] + 512) - C_M^2*e^{-df/512}*U[t][s]
//   df = 64*(dix^2+diy^2); s = ix_i+ix_j; t = iy_i+iy_j; diag = 1e-10.
// =====================================================================
__global__ void k_A(float* __restrict__ out_A)
{
    int b = blockIdx.y, tid = threadIdx.x;
    __shared__ int six[100], siy[100];
    if (tid < 100) {
        int mind = g_minds[b*MMM + tid];
        six[tid] = mind & 63;
        siy[tid] = mind >> 6;
    }
    __syncthreads();
    int p = blockIdx.x * 256 + tid;
    if (p < 4950) {
        int i, j;
        pair_ij(p, i, j);
        int ixi = six[i], ixj = six[j];
        int iyi = siy[i], iyj = siy[j];
        int s = ixi + ixj, t = iyi + iyj;
        float Tv = g_T[b][t][s];
        float Uv = g_U[b][t][s];
        int dix = ixi - ixj, diy = iyi - iyj;
        float d2 = (float)(dix*dix + diy*diy);      // df/64, exact
        float e1 = __expf(-0.25f  * d2);            // exp(-df/256)
        float e2 = __expf(-0.125f * d2);            // exp(-df/512)
        float Aij = C_M * e1 * (C_H * Tv + 512.0f) - C_M2 * e2 * Uv;
        out_A[b*10000 + i*100 + j] = Aij;
        out_A[b*10000 + j*100 + i] = Aij;
    }
    if (blockIdx.x == 0 && tid < 100)
        out_A[b*10000 + tid*101] = 1e-10f;
}

// =====================================================================
// L4: Bm = diag(1/vM) - inv(A + diag(vM)).
// fp32 in-smem Gauss-Jordan, partial pivoting, 3 barriers/step.
// =====================================================================
__global__ void __launch_bounds__(512, 1) k_inv(const float* __restrict__ out_A,
                                                float* __restrict__ out_Bm)
{
    __shared__ float sA[100][101];
    __shared__ float rowk[104];
    __shared__ float colk[104];
    __shared__ float svm[100];
    __shared__ int piv[100];
    __shared__ int cperm[100];
    __shared__ int s_pr;
    __shared__ float s_pinv;

    int b = blockIdx.x, tid = threadIdx.x;
    if (tid < 100) svm[tid] = g_vM[b*MMM + tid];
    __syncthreads();
    for (int idx = tid; idx < 10000; idx += 512) {
        int ii = idx / 100, jc = idx - ii*100;
        float val = out_A[b*10000 + idx];
        if (ii == jc) val += svm[ii];
        sA[ii][jc] = val;
    }

    int jj = tid % 100;
    int rg = tid / 100;
    bool act = (tid < 500);
    __syncthreads();

    for (int k = 0; k < 100; k++) {
        if (tid < 32) {
            float bv = -1.0f; int br = 0x7FFFFFFF;
#pragma unroll
            for (int q = 0; q < 4; q++) {
                int r = k + tid + (q << 5);
                if (r < 100) {
                    float av = fabsf(sA[r][k]);
                    if (av > bv) { bv = av; br = r; }
                }
            }
#pragma unroll
            for (int off = 16; off; off >>= 1) {
                float ov = __shfl_down_sync(0xFFFFFFFFu, bv, off);
                int   oi = __shfl_down_sync(0xFFFFFFFFu, br, off);
                if (ov > bv || (ov == bv && oi < br)) { bv = ov; br = oi; }
            }
            if (tid == 0) {
                s_pr = br; piv[k] = br;
                s_pinv = 1.0f / sA[br][k];
            }
        }
        __syncthreads();
        int pr = s_pr;
        float pinv = s_pinv;
        if (tid < 100) {
            int c = tid;
            float told_k = sA[k][c];
            float told_p = sA[pr][c];
            float rv = (c == k) ? pinv : told_p * pinv;
            rowk[c] = rv;
            sA[k][c] = rv;
            if (pr != k) {
                if (c == k) { colk[pr] = told_k; sA[pr][k] = 0.0f; }
                else        { sA[pr][c] = told_k; }
            }
        } else if (tid >= 256 && tid < 356) {
            int r = tid - 256;
            if (r != k && r != pr) {
                colk[r] = sA[r][k];
                sA[r][k] = 0.0f;
            }
        }
        __syncthreads();
        if (act) {
            float rk = rowk[jj];
#pragma unroll
            for (int t = 0; t < 20; t++) {
                int rr = rg + t*5;
                if (rr != k) sA[rr][jj] -= colk[rr] * rk;
            }
        }
        __syncthreads();
    }
    if (tid == 0) {
        for (int j2 = 0; j2 < 100; j2++) cperm[j2] = j2;
        for (int k = 99; k >= 0; k--) {
            int pp = piv[k];
            int t = cperm[k]; cperm[k] = cperm[pp]; cperm[pp] = t;
        }
    }
    __syncthreads();
    for (int idx = tid; idx < 10000; idx += 512) {
        int ii = idx / 100, jc = idx - ii*100;
        float w = sA[ii][cperm[jc]];
        float d = (ii == jc) ? (1.0f / svm[ii]) : 0.0f;
        out_Bm[b*10000 + idx] = d - w;
    }
}

// =====================================================================
// launch
// =====================================================================
extern "C" void kernel_launch(void* const* d_in, const int* in_sizes, int n_in,
                              void* d_out, int out_size)
{
    const float* pts = (const float*)d_in[0];
    float* out       = (float*)d_out;
    float* out_m     = out;                                   // 8*512*4096
    float* out_v     = out_m + (size_t)NB*NP*GG;              // 8*4096
    float* out_A     = out_v + (size_t)NB*GG;                 // 8*100*100
    float* out_Bm    = out_A + (size_t)NB*MMM*MMM;            // 8*100*100
    float* out_minds = out_Bm + (size_t)NB*MMM*MMM;           // 8*100

    k_v_emid<<<32 + NB*NP, 256>>>(pts, out_v);
    k_sort_tab_m<<<8 + 128 + NB*NP, 256>>>(pts, out_minds, out_m);
    k_A<<<dim3(20, NB), 256>>>(out_A);
    k_inv<<<NB, 512>>>(out_A, out_Bm);
}